// round 3
// baseline (speedup 1.0000x reference)
#include <cuda_runtime.h>
#include <math.h>

// ---------------- problem constants (fixed shapes) ----------------
#define M_BOXES 512
#define N_IMGS  2
#define C_FEAT  512
#define POOLSZ  14
#define SP      196            // 14*14
#define HID     1024
#define NCLS    81
#define OCONV   256
#define KFC     100352         // C_FEAT*SP
#define KCONV   4608           // C_FEAT*9
#define SPLITK  8
#define KSLICE  (KFC/SPLITK)   // 12544
#define PART    (M_BOXES*NCLS) // 41472 (output section size)
#define MROWS   (M_BOXES*SP)   // 100352 conv-gemm rows

// ---------------- device scratch (static, no allocs) ----------------
__device__ float g_pooled[(size_t)M_BOXES*C_FEAT*SP];     // 205.5 MB
__device__ float g_partial[(size_t)SPLITK*M_BOXES*HID];   // 16 MB
__device__ float g_h[M_BOXES*HID];
__device__ float g_zsum[M_BOXES*OCONV];
__device__ float g_wt[(size_t)KCONV*OCONV];               // w_conv transposed [k][oc]
__device__ float g_boxp[M_BOXES*8];                       // sx1,sy1,sx2,sy2,lvl,bidx

// ---------------- K1: per-box FPN level + scaled coords ----------------
__global__ void k_prep(const float* __restrict__ boxes,
                       const int* __restrict__ bidx,
                       const int* __restrict__ ph, const int* __restrict__ pw) {
    int m = threadIdx.x;
    if (m >= M_BOXES) return;
    int ih = ph[0], iw = pw[0];
    // tolerate float-encoded scalars
    if (ih <= 0 || ih > 100000) ih = (int)__int_as_float(ph[0]);
    if (iw <= 0 || iw > 100000) iw = (int)__int_as_float(pw[0]);
    float alpha = (224.0f / 800.0f) * (float)min(ih, iw);

    float x1 = boxes[m*4+0], y1 = boxes[m*4+1], x2 = boxes[m*4+2], y2 = boxes[m*4+3];
    float bw = fabsf(x2 - x1), bh = fabsf(y2 - y1);
    float s  = sqrtf(fmaxf(bw*bh, 1e-6f));
    float k  = floorf(4.0f + log2f(s / alpha));
    int lvl  = (int)fminf(fmaxf(k - 2.0f, 0.0f), 3.0f);
    float scale = 1.0f / (float)(4 << lvl);

    g_boxp[m*8+0] = x1*scale;
    g_boxp[m*8+1] = y1*scale;
    g_boxp[m*8+2] = x2*scale;
    g_boxp[m*8+3] = y2*scale;
    g_boxp[m*8+4] = (float)lvl;
    g_boxp[m*8+5] = (float)bidx[m];
}

// ---------------- K2: RoIAlign (1 sample per bin center) ----------------
__global__ void __launch_bounds__(256) k_roi(const float* __restrict__ p2,
                                             const float* __restrict__ p3,
                                             const float* __restrict__ p4,
                                             const float* __restrict__ p5) {
    long long idx = (long long)blockIdx.x * blockDim.x + threadIdx.x;
    const long long total = (long long)M_BOXES * C_FEAT * SP;
    if (idx >= total) return;

    int sidx = (int)(idx % SP);
    int c    = (int)((idx / SP) % C_FEAT);
    int m    = (int)(idx / ((long long)SP * C_FEAT));
    int py = sidx / POOLSZ, px = sidx % POOLSZ;

    const float* bp = &g_boxp[m*8];
    float sx1 = bp[0], sy1 = bp[1], sx2 = bp[2], sy2 = bp[3];
    int lvl = (int)bp[4];
    int bi  = (int)bp[5];

    const float* feat = (lvl == 0) ? p2 : (lvl == 1) ? p3 : (lvl == 2) ? p4 : p5;
    int H = 200 >> lvl;
    int W = H;

    float gx = (px + 0.5f) / (float)POOLSZ;
    float gy = (py + 0.5f) / (float)POOLSZ;
    float xs = sx1 + gx * (sx2 - sx1);
    float ys = sy1 + gy * (sy2 - sy1);
    float x0f = floorf(xs), y0f = floorf(ys);
    float lx = xs - x0f, ly = ys - y0f;
    int ix0 = min(max((int)x0f, 0), W-1);
    int ix1 = min(max((int)x0f + 1, 0), W-1);
    int iy0 = min(max((int)y0f, 0), H-1);
    int iy1 = min(max((int)y0f + 1, 0), H-1);

    const float* base = feat + ((size_t)(bi * C_FEAT + c)) * (size_t)(H * W);
    float v00 = base[iy0*W + ix0];
    float v01 = base[iy0*W + ix1];
    float v10 = base[iy1*W + ix0];
    float v11 = base[iy1*W + ix1];
    float val = v00*(1.f-ly)*(1.f-lx) + v01*(1.f-ly)*lx + v10*ly*(1.f-lx) + v11*ly*lx;
    g_pooled[idx] = val;
}

// ---------------- K3: FC1 GEMM 512x100352x1024, splitK=8 ----------------
// 128x128 tile, BK=8, 256 threads, 8x8 micro-tile
__global__ void __launch_bounds__(256) k_gemm1(const float* __restrict__ B) {
    __shared__ float As[8][128];
    __shared__ float Bs[8][128];
    const float* A = g_pooled;  // [512][100352]

    int tid = threadIdx.x;
    int bn = blockIdx.x, bm = blockIdx.y, sk = blockIdx.z;
    int k0 = sk * KSLICE, kend = k0 + KSLICE;

    int arow = tid >> 1;            // 0..127
    int ak4  = (tid & 1) * 4;       // 0 or 4
    const float* Aptr = A + (size_t)(bm*128 + arow) * KFC + ak4;
    int bk  = tid >> 5;             // 0..7
    int bn4 = (tid & 31) * 4;       // 0..124
    const float* Bptr = B + (size_t)bk * HID + bn*128 + bn4;

    int tx = tid & 15, ty = tid >> 4;
    float acc[8][8];
    #pragma unroll
    for (int i = 0; i < 8; i++)
        #pragma unroll
        for (int j = 0; j < 8; j++) acc[i][j] = 0.f;

    for (int k = k0; k < kend; k += 8) {
        float4 av = *(const float4*)(Aptr + k);
        float4 bv = *(const float4*)(Bptr + (size_t)k * HID);
        __syncthreads();
        As[ak4+0][arow] = av.x;
        As[ak4+1][arow] = av.y;
        As[ak4+2][arow] = av.z;
        As[ak4+3][arow] = av.w;
        *(float4*)&Bs[bk][bn4] = bv;
        __syncthreads();
        #pragma unroll
        for (int kk = 0; kk < 8; kk++) {
            float4 a0 = *(const float4*)&As[kk][ty*8];
            float4 a1 = *(const float4*)&As[kk][ty*8+4];
            float4 b0 = *(const float4*)&Bs[kk][tx*8];
            float4 b1 = *(const float4*)&Bs[kk][tx*8+4];
            float a[8] = {a0.x,a0.y,a0.z,a0.w,a1.x,a1.y,a1.z,a1.w};
            float b[8] = {b0.x,b0.y,b0.z,b0.w,b1.x,b1.y,b1.z,b1.w};
            #pragma unroll
            for (int i = 0; i < 8; i++)
                #pragma unroll
                for (int j = 0; j < 8; j++)
                    acc[i][j] = fmaf(a[i], b[j], acc[i][j]);
        }
    }

    float* P = g_partial + ((size_t)sk * M_BOXES + (size_t)bm*128) * HID + bn*128;
    #pragma unroll
    for (int i = 0; i < 8; i++) {
        size_t ro = (size_t)(ty*8 + i) * HID + tx*8;
        *(float4*)&P[ro]   = make_float4(acc[i][0], acc[i][1], acc[i][2], acc[i][3]);
        *(float4*)&P[ro+4] = make_float4(acc[i][4], acc[i][5], acc[i][6], acc[i][7]);
    }
}

__global__ void k_reduce1(const float* __restrict__ bfc1) {
    int idx = blockIdx.x * blockDim.x + threadIdx.x;
    if (idx >= M_BOXES * HID) return;
    float v = 0.f;
    #pragma unroll
    for (int s = 0; s < SPLITK; s++)
        v += g_partial[(size_t)s * M_BOXES * HID + idx];
    v += bfc1[idx % HID];
    g_h[idx] = fmaxf(v, 0.f);
}

// ---------------- K4: cls/box heads + softmax ----------------
__global__ void __launch_bounds__(128) k_heads(const float* __restrict__ wc,
                                               const float* __restrict__ bc,
                                               const float* __restrict__ wb,
                                               const float* __restrict__ bb,
                                               float* __restrict__ out) {
    __shared__ float hrow[HID];
    __shared__ float lg[NCLS];
    __shared__ float mx, sm;
    int m = blockIdx.x, tid = threadIdx.x;
    for (int k = tid; k < HID; k += blockDim.x) hrow[k] = g_h[m*HID + k];
    __syncthreads();
    if (tid < NCLS) {
        float ac = bc[tid], ab = bb[tid];
        for (int k = 0; k < HID; k++) {
            float h = hrow[k];
            ac = fmaf(h, wc[k*NCLS + tid], ac);
            ab = fmaf(h, wb[k*NCLS + tid], ab);
        }
        lg[tid] = ac;
        out[PART + m*NCLS + tid] = ab;
    }
    __syncthreads();
    if (tid == 0) {
        float v = -1e30f;
        for (int c = 0; c < NCLS; c++) v = fmaxf(v, lg[c]);
        mx = v;
    }
    __syncthreads();
    if (tid < NCLS) lg[tid] = expf(lg[tid] - mx);
    __syncthreads();
    if (tid == 0) {
        float v = 0.f;
        for (int c = 0; c < NCLS; c++) v += lg[c];
        sm = v;
    }
    __syncthreads();
    if (tid < NCLS) out[m*NCLS + tid] = lg[tid] / sm;
}

// ---------------- K5 helpers: weight transpose + zsum zero ----------------
__global__ void k_wt(const float* __restrict__ wconv) {
    int idx = blockIdx.x * blockDim.x + threadIdx.x;
    if (idx >= OCONV * KCONV) return;
    int oc = idx / KCONV, k = idx % KCONV;
    g_wt[(size_t)k * OCONV + oc] = wconv[idx];
}

__global__ void k_zero() {
    int idx = blockIdx.x * blockDim.x + threadIdx.x;
    if (idx < M_BOXES * OCONV) g_zsum[idx] = 0.f;
}

// ---------------- K5: 3x3 conv as implicit-im2col GEMM + fused mean-reduce ----------------
// M'=100352 (box*spatial), K'=4608, N'=256; grid (2 N-tiles, 784 M-tiles)
__global__ void __launch_bounds__(256) k_convgemm(const float* __restrict__ bconv) {
    __shared__ float smem[2048];
    float (*As)[128] = (float (*)[128])smem;
    float (*Bs)[128] = (float (*)[128])(smem + 1024);

    int tid = threadIdx.x;
    int bn = blockIdx.x;                 // 0..1
    int rowbase = blockIdx.y * 128;      // 0..100224

    int arow = tid >> 1;
    int ak4  = (tid & 1) * 4;
    int grow = rowbase + arow;
    int am = grow / SP;
    int asp = grow % SP;
    int ay = asp / POOLSZ, ax = asp % POOLSZ;
    const float* Ain = g_pooled + (size_t)am * C_FEAT * SP;

    int bk  = tid >> 5;
    int bn4 = (tid & 31) * 4;
    const float* Bptr = g_wt + (size_t)bk * OCONV + bn*128 + bn4;

    int tx = tid & 15, ty = tid >> 4;
    float acc[8][8];
    #pragma unroll
    for (int i = 0; i < 8; i++)
        #pragma unroll
        for (int j = 0; j < 8; j++) acc[i][j] = 0.f;

    for (int k0 = 0; k0 < KCONV; k0 += 8) {
        float avals[4];
        #pragma unroll
        for (int kk = 0; kk < 4; kk++) {
            int k  = k0 + ak4 + kk;
            int ic = k / 9;
            int r  = k - ic*9;
            int dy = r / 3 - 1;
            int dx = r - (r/3)*3 - 1;
            int yy = ay + dy, xx = ax + dx;
            avals[kk] = (yy >= 0 && yy < POOLSZ && xx >= 0 && xx < POOLSZ)
                        ? Ain[ic*SP + yy*POOLSZ + xx] : 0.f;
        }
        float4 bv = *(const float4*)(Bptr + (size_t)k0 * OCONV);
        __syncthreads();
        As[ak4+0][arow] = avals[0];
        As[ak4+1][arow] = avals[1];
        As[ak4+2][arow] = avals[2];
        As[ak4+3][arow] = avals[3];
        *(float4*)&Bs[bk][bn4] = bv;
        __syncthreads();
        #pragma unroll
        for (int kk = 0; kk < 8; kk++) {
            float4 a0 = *(const float4*)&As[kk][ty*8];
            float4 a1 = *(const float4*)&As[kk][ty*8+4];
            float4 b0 = *(const float4*)&Bs[kk][tx*8];
            float4 b1 = *(const float4*)&Bs[kk][tx*8+4];
            float a[8] = {a0.x,a0.y,a0.z,a0.w,a1.x,a1.y,a1.z,a1.w};
            float b[8] = {b0.x,b0.y,b0.z,b0.w,b1.x,b1.y,b1.z,b1.w};
            #pragma unroll
            for (int i = 0; i < 8; i++)
                #pragma unroll
                for (int j = 0; j < 8; j++)
                    acc[i][j] = fmaf(a[i], b[j], acc[i][j]);
        }
    }

    // epilogue: z = relu(acc + b), reduce over spatial rows into g_zsum[m][oc]
    int m0 = rowbase / SP;
    int mlast = (rowbase + 127) / SP;   // m0 or m0+1 (196 > 128)
    float s0[8], s1[8];
    #pragma unroll
    for (int j = 0; j < 8; j++) { s0[j] = 0.f; s1[j] = 0.f; }
    #pragma unroll
    for (int i = 0; i < 8; i++) {
        int mi = (rowbase + ty*8 + i) / SP;
        #pragma unroll
        for (int j = 0; j < 8; j++) {
            int oc = bn*128 + tx*8 + j;
            float z = fmaxf(acc[i][j] + bconv[oc], 0.f);
            if (mi == m0) s0[j] += z; else s1[j] += z;
        }
    }
    __syncthreads();
    float* red = smem;  // 16 x 128
    #pragma unroll
    for (int j = 0; j < 8; j++) red[ty*128 + tx*8 + j] = s0[j];
    __syncthreads();
    if (ty == 0) {
        #pragma unroll
        for (int j = 0; j < 8; j++) {
            int col = tx*8 + j;
            float v = 0.f;
            #pragma unroll
            for (int t = 0; t < 16; t++) v += red[t*128 + col];
            atomicAdd(&g_zsum[m0*OCONV + bn*128 + col], v);
        }
    }
    __syncthreads();
    if (mlast != m0) {
        #pragma unroll
        for (int j = 0; j < 8; j++) red[ty*128 + tx*8 + j] = s1[j];
        __syncthreads();
        if (ty == 0) {
            #pragma unroll
            for (int j = 0; j < 8; j++) {
                int col = tx*8 + j;
                float v = 0.f;
                #pragma unroll
                for (int t = 0; t < 16; t++) v += red[t*128 + col];
                atomicAdd(&g_zsum[mlast*OCONV + bn*128 + col], v);
            }
        }
    }
}

// ---------------- K6: mask FC + sigmoid ----------------
__global__ void __launch_bounds__(128) k_maskhead(const float* __restrict__ wm,
                                                  const float* __restrict__ bm_,
                                                  float* __restrict__ out) {
    int m = blockIdx.x, t = threadIdx.x;
    if (t >= NCLS) return;
    float acc = bm_[t];
    for (int oc = 0; oc < OCONV; oc++)
        acc = fmaf(g_zsum[m*OCONV + oc] * (1.0f/196.0f), wm[oc*NCLS + t], acc);
    out[2*PART + m*NCLS + t] = 1.0f / (1.0f + expf(-acc));
}

// ---------------- launch ----------------
extern "C" void kernel_launch(void* const* d_in, const int* in_sizes, int n_in,
                              void* d_out, int out_size) {
    const float* p2     = (const float*)d_in[0];
    const float* p3     = (const float*)d_in[1];
    const float* p4     = (const float*)d_in[2];
    const float* p5     = (const float*)d_in[3];
    const float* boxes  = (const float*)d_in[4];
    const int*   bidx   = (const int*)  d_in[5];
    const float* w_fc1  = (const float*)d_in[6];
    const float* b_fc1  = (const float*)d_in[7];
    const float* w_cls  = (const float*)d_in[8];
    const float* b_cls  = (const float*)d_in[9];
    const float* w_box  = (const float*)d_in[10];
    const float* b_box  = (const float*)d_in[11];
    const float* w_conv = (const float*)d_in[12];
    const float* b_conv = (const float*)d_in[13];
    const float* w_mfc  = (const float*)d_in[14];
    const float* b_mfc  = (const float*)d_in[15];
    const int*   img_h  = (const int*)  d_in[16];
    const int*   img_w  = (const int*)  d_in[17];
    float* out = (float*)d_out;

    k_prep<<<1, 512>>>(boxes, bidx, img_h, img_w);
    k_wt<<<(OCONV*KCONV + 255)/256, 256>>>(w_conv);
    k_zero<<<(M_BOXES*OCONV + 255)/256, 256>>>();

    long long roi_total = (long long)M_BOXES * C_FEAT * SP;
    k_roi<<<(unsigned)((roi_total + 255)/256), 256>>>(p2, p3, p4, p5);

    k_gemm1<<<dim3(HID/128, M_BOXES/128, SPLITK), 256>>>(w_fc1);
    k_reduce1<<<(M_BOXES*HID + 255)/256, 256>>>(b_fc1);
    k_heads<<<M_BOXES, 128>>>(w_cls, b_cls, w_box, b_box, out);

    k_convgemm<<<dim3(OCONV/128, MROWS/128), 256>>>(b_conv);
    k_maskhead<<<M_BOXES, 128>>>(w_mfc, b_mfc, out);
}